// round 2
// baseline (speedup 1.0000x reference)
#include <cuda_runtime.h>

#define RADIUS 5
#define TX     32
#define TY     8
#define SW     (TX + 2*RADIUS)      /* 42 */
#define SH     (TY + RADIUS)        /* 13: only bottom halo needed (symmetric pairs) */
#define NB     8
#define NK     4
#define IMH    224
#define IMW    224

// log2(e) folded into the Gaussian exponents so the weight is a single exp2f.
#define C_INT  (-0.014426950408889634f)          /* -log2e / 100      */
#define C_DST  (-0.09016844005555897f)           /* -log2e / 16       */

// Global accumulators: [b][k][{A,B}] as double. Zero-initialized at load;
// k_final re-zeros them after reading, so every graph replay is clean.
__device__ double g_acc[NB * NK * 2];

__global__ __launch_bounds__(TX * TY) void k_main(const float* __restrict__ images,
                                                  const float* __restrict__ labels) {
    __shared__ float  s_img[SH * SW];
    __shared__ float4 s_lab[SH * SW];
    __shared__ float  s_red[TY][8];

    const int tx  = threadIdx.x;
    const int ty  = threadIdx.y;
    const int tid = ty * TX + tx;
    const int b   = blockIdx.z;
    const int y0  = blockIdx.y * TY;
    const int x0  = blockIdx.x * TX;

    const float* imgb = images + (size_t)b * IMH * IMW;
    const float* labb = labels + (size_t)b * NK * IMH * IMW;

    // Halo: y in [y0, y0+TY+RADIUS), x in [x0-RADIUS, x0+TX+RADIUS).
    // Out-of-image: image sentinel 1e10 -> weight underflows to exactly 0
    // (this implements the mask, symmetrically); labels 0.
    for (int i = tid; i < SH * SW; i += TX * TY) {
        int sy = i / SW;
        int sx = i - sy * SW;
        int gy = y0 + sy;
        int gx = x0 + sx - RADIUS;
        bool in = ((unsigned)gy < IMH) && ((unsigned)gx < IMW);
        int g = gy * IMW + gx;
        s_img[i] = in ? imgb[g] * 255.0f : 1e10f;
        float4 L = make_float4(0.f, 0.f, 0.f, 0.f);
        if (in) {
            L.x = labb[0 * IMH * IMW + g];
            L.y = labb[1 * IMH * IMW + g];
            L.z = labb[2 * IMH * IMW + g];
            L.w = labb[3 * IMH * IMW + g];
        }
        s_lab[i] = L;
    }
    __syncthreads();

    const int    cidx = ty * SW + tx + RADIUS;
    const float  c    = s_img[cidx];
    const float4 p    = s_lab[cidx];

    // Positive-offset accumulators: S1 = sum w, S2k = sum w * p_k(j)
    float S1 = 0.f;
    float s20 = 0.f, s21 = 0.f, s22 = 0.f, s23 = 0.f;

    // dy = 0, dx = 1..RADIUS
    #pragma unroll
    for (int dx = 1; dx <= RADIUS; dx++) {
        const int   j    = cidx + dx;
        const float r    = s_img[j];
        const float diff = r - c;
        const float arg  = fmaf(diff * diff, C_INT, C_DST * (float)(dx * dx));
        const float w    = exp2f(arg);
        const float4 q   = s_lab[j];
        S1 += w;
        s20 = fmaf(w, q.x, s20);
        s21 = fmaf(w, q.y, s21);
        s22 = fmaf(w, q.z, s22);
        s23 = fmaf(w, q.w, s23);
    }
    // dy = 1..RADIUS, dx = -RADIUS..RADIUS
    #pragma unroll
    for (int dy = 1; dy <= RADIUS; dy++) {
        const int base = cidx + dy * SW;
        #pragma unroll
        for (int dx = -RADIUS; dx <= RADIUS; dx++) {
            const int   j    = base + dx;
            const float r    = s_img[j];
            const float diff = r - c;
            const float arg  = fmaf(diff * diff, C_INT,
                                    C_DST * (float)(dy * dy + dx * dx));
            const float w    = exp2f(arg);
            const float4 q   = s_lab[j];
            S1 += w;
            s20 = fmaf(w, q.x, s20);
            s21 = fmaf(w, q.y, s21);
            s22 = fmaf(w, q.z, s22);
            s23 = fmaf(w, q.w, s23);
        }
    }

    // Symmetric closure:
    //   A_k = sum_i p_k * (p_k + 2*S2_k)     (w_ii = 1)
    //   B_k = sum_i p_k * (1 + S1) + S2_k
    const float g1 = 1.f + S1;
    float v[8] = {
        p.x * fmaf(2.f, s20, p.x), p.y * fmaf(2.f, s21, p.y),
        p.z * fmaf(2.f, s22, p.z), p.w * fmaf(2.f, s23, p.w),
        fmaf(p.x, g1, s20),        fmaf(p.y, g1, s21),
        fmaf(p.z, g1, s22),        fmaf(p.w, g1, s23)
    };

    #pragma unroll
    for (int jj = 0; jj < 8; jj++) {
        float s = v[jj];
        #pragma unroll
        for (int o = 16; o > 0; o >>= 1)
            s += __shfl_xor_sync(0xffffffffu, s, o);
        if (tx == 0) s_red[ty][jj] = s;
    }
    __syncthreads();

    if (tid < 8) {
        float s = 0.f;
        #pragma unroll
        for (int w = 0; w < TY; w++) s += s_red[w][tid];
        const int k     = tid & 3;
        const int which = tid >> 2;
        atomicAdd(&g_acc[(b * NK + k) * 2 + which], (double)s);
    }
}

__global__ void k_final(float* out) {
    __shared__ double sh[NB * NK * 2];
    const int t = threadIdx.x;
    if (t < NB * NK * 2) sh[t] = g_acc[t];
    __syncthreads();
    if (t == 0) {
        double acc = 0.0;
        for (int b = 0; b < NB; b++)
            for (int k = 0; k < NK; k++) {
                double A  = sh[(b * NK + k) * 2 + 0];
                double Bv = sh[(b * NK + k) * 2 + 1];
                acc += fabs(A / Bv);
            }
        out[0] = (float)((double)NK - acc / (double)NB);
    }
    // Reset for the next (graph-replayed) run.
    if (t < NB * NK * 2) g_acc[t] = 0.0;
}

extern "C" void kernel_launch(void* const* d_in, const int* in_sizes, int n_in,
                              void* d_out, int out_size) {
    const float* images = (const float*)d_in[0];
    const float* labels = (const float*)d_in[1];
    if (n_in >= 2 && in_sizes[0] > in_sizes[1]) {   // robust to input ordering
        images = (const float*)d_in[1];
        labels = (const float*)d_in[0];
    }

    dim3 grid(IMW / TX, IMH / TY, NB);
    dim3 blk(TX, TY);
    k_main<<<grid, blk>>>(images, labels);
    k_final<<<1, 64>>>((float*)d_out);
}

// round 4
// speedup vs baseline: 2.1185x; 2.1185x over previous
#include <cuda_runtime.h>

#define RADIUS 5
#define TX     32
#define TY     8
#define SW     (TX + 2*RADIUS)      /* 42 */
#define SH     (TY + RADIUS)        /* 13: bottom halo only (symmetric pairs) */
#define NB     8
#define NK     4
#define IMH    224
#define IMW    224
#define NBLK   ((IMW/TX) * (IMH/TY) * NB)   /* 1568 */

// log2(e) folded into the Gaussian exponents -> single exp2f per neighbor.
#define C_INT  (-0.014426950408889634f)      /* -log2e / 100 */
#define C_DST  (-0.09016844005555897f)       /* -log2e / 16  */

// Accumulators [b][k][{A,B}] (double) + completion counter. Zero-initialized
// at module load; the last block resets them each run, so graph replays are
// deterministic.
__device__ double       g_acc[NB * NK * 2];
__device__ unsigned int g_count;

__global__ __launch_bounds__(TX * TY) void k_main(const float* __restrict__ images,
                                                  const float* __restrict__ labels,
                                                  float* __restrict__ out) {
    __shared__ float  s_img[SH * SW];
    __shared__ float4 s_lab[SH * SW];
    __shared__ float  s_red[TY][8];
    __shared__ bool   s_last;

    const int tx  = threadIdx.x;
    const int ty  = threadIdx.y;
    const int tid = ty * TX + tx;
    const int b   = blockIdx.z;
    const int y0  = blockIdx.y * TY;
    const int x0  = blockIdx.x * TX;

    const float* imgb = images + (size_t)b * IMH * IMW;
    const float* labb = labels + (size_t)b * NK * IMH * IMW;

    // Halo: y in [y0, y0+TY+RADIUS), x in [x0-RADIUS, x0+TX+RADIUS).
    // Out-of-image: image sentinel 1e10 -> weight underflows to exactly 0
    // (implements the mask symmetrically); labels 0.
    for (int i = tid; i < SH * SW; i += TX * TY) {
        int sy = i / SW;
        int sx = i - sy * SW;
        int gy = y0 + sy;
        int gx = x0 + sx - RADIUS;
        bool in = ((unsigned)gy < IMH) && ((unsigned)gx < IMW);
        int g = gy * IMW + gx;
        s_img[i] = in ? imgb[g] * 255.0f : 1e10f;
        float4 L = make_float4(0.f, 0.f, 0.f, 0.f);
        if (in) {
            L.x = labb[0 * IMH * IMW + g];
            L.y = labb[1 * IMH * IMW + g];
            L.z = labb[2 * IMH * IMW + g];
            L.w = labb[3 * IMH * IMW + g];
        }
        s_lab[i] = L;
    }
    __syncthreads();

    const int    cidx = ty * SW + tx + RADIUS;
    const float  c    = s_img[cidx];
    const float4 p    = s_lab[cidx];

    // Positive-offset accumulators: S1 = sum w, S2k = sum w * p_k(j)
    float S1 = 0.f;
    float s20 = 0.f, s21 = 0.f, s22 = 0.f, s23 = 0.f;

    #pragma unroll
    for (int dx = 1; dx <= RADIUS; dx++) {           // dy = 0 row
        const int   j    = cidx + dx;
        const float r    = s_img[j];
        const float diff = r - c;
        const float arg  = fmaf(diff * diff, C_INT, C_DST * (float)(dx * dx));
        const float w    = exp2f(arg);
        const float4 q   = s_lab[j];
        S1 += w;
        s20 = fmaf(w, q.x, s20);
        s21 = fmaf(w, q.y, s21);
        s22 = fmaf(w, q.z, s22);
        s23 = fmaf(w, q.w, s23);
    }
    #pragma unroll
    for (int dy = 1; dy <= RADIUS; dy++) {           // dy > 0 rows
        const int base = cidx + dy * SW;
        #pragma unroll
        for (int dx = -RADIUS; dx <= RADIUS; dx++) {
            const int   j    = base + dx;
            const float r    = s_img[j];
            const float diff = r - c;
            const float arg  = fmaf(diff * diff, C_INT,
                                    C_DST * (float)(dy * dy + dx * dx));
            const float w    = exp2f(arg);
            const float4 q   = s_lab[j];
            S1 += w;
            s20 = fmaf(w, q.x, s20);
            s21 = fmaf(w, q.y, s21);
            s22 = fmaf(w, q.z, s22);
            s23 = fmaf(w, q.w, s23);
        }
    }

    // Symmetric closure (w_ii = 1):
    //   A_k = sum_i p_k * (p_k + 2*S2_k)
    //   B_k = sum_i p_k * (1 + S1) + S2_k
    const float g1 = 1.f + S1;
    float v[8] = {
        p.x * fmaf(2.f, s20, p.x), p.y * fmaf(2.f, s21, p.y),
        p.z * fmaf(2.f, s22, p.z), p.w * fmaf(2.f, s23, p.w),
        fmaf(p.x, g1, s20),        fmaf(p.y, g1, s21),
        fmaf(p.z, g1, s22),        fmaf(p.w, g1, s23)
    };

    #pragma unroll
    for (int jj = 0; jj < 8; jj++) {
        float s = v[jj];
        #pragma unroll
        for (int o = 16; o > 0; o >>= 1)
            s += __shfl_xor_sync(0xffffffffu, s, o);
        if (tx == 0) s_red[ty][jj] = s;
    }
    __syncthreads();

    if (tid < 8) {
        float s = 0.f;
        #pragma unroll
        for (int w = 0; w < TY; w++) s += s_red[w][tid];
        const int k     = tid & 3;
        const int which = tid >> 2;   // 0 = A (num side), 1 = B (den side)
        atomicAdd(&g_acc[(b * NK + k) * 2 + which], (double)s);
    }

    // ---- last-block finalize (replaces a second kernel launch) ----
    __threadfence();                   // publish our atomics before counting
    if (tid == 0)
        s_last = (atomicAdd(&g_count, 1u) == NBLK - 1u);
    __syncthreads();

    if (s_last) {
        __threadfence();               // acquire: see all blocks' g_acc
        if (tid < NB * NK) {           // 32 parallel double divides (pipelined)
            double A  = g_acc[tid * 2 + 0];
            double Bv = g_acc[tid * 2 + 1];
            double r  = fabs(A / Bv);
            #pragma unroll
            for (int o = 16; o > 0; o >>= 1)
                r += __shfl_xor_sync(0xffffffffu, r, o);
            if (tid == 0)
                out[0] = (float)((double)NK - r / (double)NB);
        }
        __syncthreads();
        // Reset state for the next graph replay.
        if (tid < NB * NK * 2) g_acc[tid] = 0.0;
        if (tid == 0) g_count = 0u;
    }
}

extern "C" void kernel_launch(void* const* d_in, const int* in_sizes, int n_in,
                              void* d_out, int out_size) {
    const float* images = (const float*)d_in[0];
    const float* labels = (const float*)d_in[1];
    if (n_in >= 2 && in_sizes[0] > in_sizes[1]) {   // robust to input ordering
        images = (const float*)d_in[1];
        labels = (const float*)d_in[0];
    }

    dim3 grid(IMW / TX, IMH / TY, NB);
    dim3 blk(TX, TY);
    k_main<<<grid, blk>>>(images, labels, (float*)d_out);
}

// round 5
// speedup vs baseline: 2.5610x; 1.2088x over previous
#include <cuda_runtime.h>

#define RADIUS 5
#define TX     32
#define TY     8                     /* threads in y; each owns 2 pixel rows */
#define PY     (2*TY)                /* 16 pixel rows per block */
#define SW     (TX + 2*RADIUS)       /* 42 */
#define SH     (PY + RADIUS)         /* 21: bottom halo only (symmetric pairs) */
#define NB     8
#define NK     4
#define IMH    224
#define IMW    224
#define NBLK   ((IMW/TX) * (IMH/PY) * NB)   /* 7*14*8 = 784 */

// log2(e) folded into the Gaussian exponents -> single EX2 per evaluation.
#define C_INT  (-0.014426950408889634f)      /* -log2e / 100 */
#define C_DST  (-0.09016844005555897f)       /* -log2e / 16  */

// [b][k][{A,B}] accumulators (double) + completion counter. Zero at load;
// the last block resets them, so graph replays are deterministic.
__device__ double       g_acc[NB * NK * 2];
__device__ unsigned int g_count;

__global__ __launch_bounds__(TX * TY) void k_main(const float* __restrict__ images,
                                                  const float* __restrict__ labels,
                                                  float* __restrict__ out) {
    __shared__ float  s_img[SH * SW];
    __shared__ float4 s_lab[SH * SW];
    __shared__ float  s_red[TY][8];
    __shared__ bool   s_last;

    const int tx  = threadIdx.x;
    const int ty  = threadIdx.y;
    const int tid = ty * TX + tx;
    const int b   = blockIdx.z;
    const int y0  = blockIdx.y * PY;
    const int x0  = blockIdx.x * TX;

    const float* imgb = images + (size_t)b * IMH * IMW;
    const float* labb = labels + (size_t)b * NK * IMH * IMW;

    // Halo: y in [y0, y0+PY+RADIUS), x in [x0-RADIUS, x0+TX+RADIUS).
    // Out-of-image: image sentinel 1e10 -> weight underflows to exactly 0
    // (implements the boundary mask symmetrically); labels 0.
    for (int i = tid; i < SH * SW; i += TX * TY) {
        int sy = i / SW;
        int sx = i - sy * SW;
        int gy = y0 + sy;
        int gx = x0 + sx - RADIUS;
        bool in = ((unsigned)gy < IMH) && ((unsigned)gx < IMW);
        int g = gy * IMW + gx;
        s_img[i] = in ? imgb[g] * 255.0f : 1e10f;
        float4 L = make_float4(0.f, 0.f, 0.f, 0.f);
        if (in) {
            L.x = labb[0 * IMH * IMW + g];
            L.y = labb[1 * IMH * IMW + g];
            L.z = labb[2 * IMH * IMW + g];
            L.w = labb[3 * IMH * IMW + g];
        }
        s_lab[i] = L;
    }
    __syncthreads();

    // Two vertically adjacent centers per thread: rows 2*ty and 2*ty+1.
    const int    ci1 = (2 * ty) * SW + tx + RADIUS;
    const int    ci2 = ci1 + SW;
    const float  c1  = s_img[ci1];
    const float  c2  = s_img[ci2];
    const float4 p1  = s_lab[ci1];
    const float4 p2  = s_lab[ci2];

    // Positive-offset accumulators per center: S1 = sum w, S2k = sum w*p_k(j)
    float S1a = 0.f, a0 = 0.f, a1 = 0.f, a2 = 0.f, a3 = 0.f;
    float S1b = 0.f, b0 = 0.f, b1 = 0.f, b2 = 0.f, b3 = 0.f;

    // --- row 2*ty: center-1 dy=0, dx=1..R ---
    #pragma unroll
    for (int dx = 1; dx <= RADIUS; dx++) {
        const int    j  = ci1 + dx;
        const float  r  = s_img[j];
        const float4 q  = s_lab[j];
        const float  d1 = r - c1;
        const float  w1 = exp2f(fmaf(d1 * d1, C_INT, C_DST * (float)(dx * dx)));
        S1a += w1;
        a0 = fmaf(w1, q.x, a0); a1 = fmaf(w1, q.y, a1);
        a2 = fmaf(w1, q.z, a2); a3 = fmaf(w1, q.w, a3);
    }
    // --- row 2*ty+1: center-1 dy=1 (all dx); center-2 dy=0 (dx>=1) ---
    #pragma unroll
    for (int dx = -RADIUS; dx <= RADIUS; dx++) {
        const int    j  = ci2 + dx;
        const float  r  = s_img[j];
        const float4 q  = s_lab[j];
        const float  d1 = r - c1;
        const float  w1 = exp2f(fmaf(d1 * d1, C_INT, C_DST * (float)(1 + dx * dx)));
        S1a += w1;
        a0 = fmaf(w1, q.x, a0); a1 = fmaf(w1, q.y, a1);
        a2 = fmaf(w1, q.z, a2); a3 = fmaf(w1, q.w, a3);
        if (dx >= 1) {      // compile-time resolved
            const float d2 = r - c2;
            const float w2 = exp2f(fmaf(d2 * d2, C_INT, C_DST * (float)(dx * dx)));
            S1b += w2;
            b0 = fmaf(w2, q.x, b0); b1 = fmaf(w2, q.y, b1);
            b2 = fmaf(w2, q.z, b2); b3 = fmaf(w2, q.w, b3);
        }
    }
    // --- rows 2*ty+o, o=2..R: center-1 dy=o, center-2 dy=o-1, all dx ---
    #pragma unroll
    for (int o = 2; o <= RADIUS; o++) {
        const int base = ci1 + o * SW;
        #pragma unroll
        for (int dx = -RADIUS; dx <= RADIUS; dx++) {
            const int    j  = base + dx;
            const float  r  = s_img[j];
            const float4 q  = s_lab[j];
            const float  d1 = r - c1;
            const float  w1 = exp2f(fmaf(d1 * d1, C_INT,
                                         C_DST * (float)(o * o + dx * dx)));
            S1a += w1;
            a0 = fmaf(w1, q.x, a0); a1 = fmaf(w1, q.y, a1);
            a2 = fmaf(w1, q.z, a2); a3 = fmaf(w1, q.w, a3);
            const float d2 = r - c2;
            const float w2 = exp2f(fmaf(d2 * d2, C_INT,
                                        C_DST * (float)((o - 1) * (o - 1) + dx * dx)));
            S1b += w2;
            b0 = fmaf(w2, q.x, b0); b1 = fmaf(w2, q.y, b1);
            b2 = fmaf(w2, q.z, b2); b3 = fmaf(w2, q.w, b3);
        }
    }
    // --- row 2*ty+R+1: center-2 dy=R, all dx ---
    {
        const int base = ci2 + RADIUS * SW;
        #pragma unroll
        for (int dx = -RADIUS; dx <= RADIUS; dx++) {
            const int    j  = base + dx;
            const float  r  = s_img[j];
            const float4 q  = s_lab[j];
            const float  d2 = r - c2;
            const float  w2 = exp2f(fmaf(d2 * d2, C_INT,
                                         C_DST * (float)(RADIUS * RADIUS + dx * dx)));
            S1b += w2;
            b0 = fmaf(w2, q.x, b0); b1 = fmaf(w2, q.y, b1);
            b2 = fmaf(w2, q.z, b2); b3 = fmaf(w2, q.w, b3);
        }
    }

    // Symmetric closure (w_ii = 1), both centers summed:
    //   A_k += p_k*(p_k + 2*S2_k);   B_k += p_k*(1+S1) + S2_k
    const float g1a = 1.f + S1a;
    const float g1b = 1.f + S1b;
    float v[8] = {
        p1.x * fmaf(2.f, a0, p1.x) + p2.x * fmaf(2.f, b0, p2.x),
        p1.y * fmaf(2.f, a1, p1.y) + p2.y * fmaf(2.f, b1, p2.y),
        p1.z * fmaf(2.f, a2, p1.z) + p2.z * fmaf(2.f, b2, p2.z),
        p1.w * fmaf(2.f, a3, p1.w) + p2.w * fmaf(2.f, b3, p2.w),
        fmaf(p1.x, g1a, a0) + fmaf(p2.x, g1b, b0),
        fmaf(p1.y, g1a, a1) + fmaf(p2.y, g1b, b1),
        fmaf(p1.z, g1a, a2) + fmaf(p2.z, g1b, b2),
        fmaf(p1.w, g1a, a3) + fmaf(p2.w, g1b, b3)
    };

    #pragma unroll
    for (int jj = 0; jj < 8; jj++) {
        float s = v[jj];
        #pragma unroll
        for (int o = 16; o > 0; o >>= 1)
            s += __shfl_xor_sync(0xffffffffu, s, o);
        if (tx == 0) s_red[ty][jj] = s;
    }
    __syncthreads();

    if (tid < 8) {
        float s = 0.f;
        #pragma unroll
        for (int w = 0; w < TY; w++) s += s_red[w][tid];
        const int k     = tid & 3;
        const int which = tid >> 2;   // 0 = A (num), 1 = B (den)
        atomicAdd(&g_acc[(b * NK + k) * 2 + which], (double)s);
    }

    // ---- last-block finalize ----
    __threadfence();
    if (tid == 0)
        s_last = (atomicAdd(&g_count, 1u) == NBLK - 1u);
    __syncthreads();

    if (s_last) {
        __threadfence();
        if (tid < NB * NK) {           // 32 parallel double divides
            double A  = g_acc[tid * 2 + 0];
            double Bv = g_acc[tid * 2 + 1];
            double r  = fabs(A / Bv);
            #pragma unroll
            for (int o = 16; o > 0; o >>= 1)
                r += __shfl_xor_sync(0xffffffffu, r, o);
            if (tid == 0)
                out[0] = (float)((double)NK - r / (double)NB);
        }
        __syncthreads();
        if (tid < NB * NK * 2) g_acc[tid] = 0.0;
        if (tid == 0) g_count = 0u;
    }
}

extern "C" void kernel_launch(void* const* d_in, const int* in_sizes, int n_in,
                              void* d_out, int out_size) {
    const float* images = (const float*)d_in[0];
    const float* labels = (const float*)d_in[1];
    if (n_in >= 2 && in_sizes[0] > in_sizes[1]) {   // robust to input ordering
        images = (const float*)d_in[1];
        labels = (const float*)d_in[0];
    }

    dim3 grid(IMW / TX, IMH / PY, NB);
    dim3 blk(TX, TY);
    k_main<<<grid, blk>>>(images, labels, (float*)d_out);
}

// round 6
// speedup vs baseline: 2.6582x; 1.0380x over previous
#include <cuda_runtime.h>

#define RADIUS 5
#define TX     32
#define TY     8                     /* threads in y; each owns 2 pixel rows */
#define PY     (2*TY)                /* 16 pixel rows per block */
#define SW     (TX + 2*RADIUS)       /* 42 */
#define SH     (PY + RADIUS)         /* 21: bottom halo only (symmetric pairs) */
#define NB     8
#define NK     4
#define IMH    224
#define IMW    224
#define NBLK   ((IMW/TX) * (IMH/PY) * NB)   /* 7*14*8 = 784 */

// log2(e) folded into the Gaussian exponents -> single MUFU.EX2 per evaluation.
#define C_INT  (-0.014426950408889634f)      /* -log2e / 100 */
#define C_DST  (-0.09016844005555897f)       /* -log2e / 16  */

// Raw hardware exp2: one MUFU instruction regardless of -use_fast_math.
// (libdevice exp2f without fast-math is a multi-instruction accurate routine.)
__device__ __forceinline__ float ex2(float x) {
    float y;
    asm("ex2.approx.ftz.f32 %0, %1;" : "=f"(y) : "f"(x));
    return y;
}

// [b][k][{A,B}] accumulators (double) + completion counter. Zero at load;
// the last block resets them, so graph replays are deterministic.
__device__ double       g_acc[NB * NK * 2];
__device__ unsigned int g_count;

__global__ __launch_bounds__(TX * TY) void k_main(const float* __restrict__ images,
                                                  const float* __restrict__ labels,
                                                  float* __restrict__ out) {
    __shared__ float  s_img[SH * SW];
    __shared__ float4 s_lab[SH * SW];
    __shared__ float  s_red[TY][8];
    __shared__ bool   s_last;

    const int tx  = threadIdx.x;
    const int ty  = threadIdx.y;
    const int tid = ty * TX + tx;
    const int b   = blockIdx.z;
    const int y0  = blockIdx.y * PY;
    const int x0  = blockIdx.x * TX;

    const float* imgb = images + (size_t)b * IMH * IMW;
    const float* labb = labels + (size_t)b * NK * IMH * IMW;

    // Halo: y in [y0, y0+PY+RADIUS), x in [x0-RADIUS, x0+TX+RADIUS).
    // Out-of-image: image sentinel 1e10 -> weight underflows to exactly 0
    // (implements the boundary mask symmetrically); labels 0.
    for (int i = tid; i < SH * SW; i += TX * TY) {
        int sy = i / SW;
        int sx = i - sy * SW;
        int gy = y0 + sy;
        int gx = x0 + sx - RADIUS;
        bool in = ((unsigned)gy < IMH) && ((unsigned)gx < IMW);
        int g = gy * IMW + gx;
        s_img[i] = in ? imgb[g] * 255.0f : 1e10f;
        float4 L = make_float4(0.f, 0.f, 0.f, 0.f);
        if (in) {
            L.x = labb[0 * IMH * IMW + g];
            L.y = labb[1 * IMH * IMW + g];
            L.z = labb[2 * IMH * IMW + g];
            L.w = labb[3 * IMH * IMW + g];
        }
        s_lab[i] = L;
    }
    __syncthreads();

    // Two vertically adjacent centers per thread: rows 2*ty and 2*ty+1.
    const int    ci1 = (2 * ty) * SW + tx + RADIUS;
    const int    ci2 = ci1 + SW;
    const float  c1  = s_img[ci1];
    const float  c2  = s_img[ci2];
    const float4 p1  = s_lab[ci1];
    const float4 p2  = s_lab[ci2];

    // Positive-offset accumulators per center: S1 = sum w, S2k = sum w*p_k(j)
    float S1a = 0.f, a0 = 0.f, a1 = 0.f, a2 = 0.f, a3 = 0.f;
    float S1b = 0.f, b0 = 0.f, b1 = 0.f, b2 = 0.f, b3 = 0.f;

    // --- row 2*ty: center-1 dy=0, dx=1..R ---
    #pragma unroll
    for (int dx = 1; dx <= RADIUS; dx++) {
        const int    j  = ci1 + dx;
        const float  r  = s_img[j];
        const float4 q  = s_lab[j];
        const float  d1 = r - c1;
        const float  w1 = ex2(fmaf(d1 * d1, C_INT, C_DST * (float)(dx * dx)));
        S1a += w1;
        a0 = fmaf(w1, q.x, a0); a1 = fmaf(w1, q.y, a1);
        a2 = fmaf(w1, q.z, a2); a3 = fmaf(w1, q.w, a3);
    }
    // --- row 2*ty+1: center-1 dy=1 (all dx); center-2 dy=0 (dx>=1) ---
    #pragma unroll
    for (int dx = -RADIUS; dx <= RADIUS; dx++) {
        const int    j  = ci2 + dx;
        const float  r  = s_img[j];
        const float4 q  = s_lab[j];
        const float  d1 = r - c1;
        const float  w1 = ex2(fmaf(d1 * d1, C_INT, C_DST * (float)(1 + dx * dx)));
        S1a += w1;
        a0 = fmaf(w1, q.x, a0); a1 = fmaf(w1, q.y, a1);
        a2 = fmaf(w1, q.z, a2); a3 = fmaf(w1, q.w, a3);
        if (dx >= 1) {      // compile-time resolved
            const float d2 = r - c2;
            const float w2 = ex2(fmaf(d2 * d2, C_INT, C_DST * (float)(dx * dx)));
            S1b += w2;
            b0 = fmaf(w2, q.x, b0); b1 = fmaf(w2, q.y, b1);
            b2 = fmaf(w2, q.z, b2); b3 = fmaf(w2, q.w, b3);
        }
    }
    // --- rows 2*ty+o, o=2..R: center-1 dy=o, center-2 dy=o-1, all dx ---
    #pragma unroll
    for (int o = 2; o <= RADIUS; o++) {
        const int base = ci1 + o * SW;
        #pragma unroll
        for (int dx = -RADIUS; dx <= RADIUS; dx++) {
            const int    j  = base + dx;
            const float  r  = s_img[j];
            const float4 q  = s_lab[j];
            const float  d1 = r - c1;
            const float  w1 = ex2(fmaf(d1 * d1, C_INT,
                                       C_DST * (float)(o * o + dx * dx)));
            S1a += w1;
            a0 = fmaf(w1, q.x, a0); a1 = fmaf(w1, q.y, a1);
            a2 = fmaf(w1, q.z, a2); a3 = fmaf(w1, q.w, a3);
            const float d2 = r - c2;
            const float w2 = ex2(fmaf(d2 * d2, C_INT,
                                      C_DST * (float)((o - 1) * (o - 1) + dx * dx)));
            S1b += w2;
            b0 = fmaf(w2, q.x, b0); b1 = fmaf(w2, q.y, b1);
            b2 = fmaf(w2, q.z, b2); b3 = fmaf(w2, q.w, b3);
        }
    }
    // --- row 2*ty+R+1: center-2 dy=R, all dx ---
    {
        const int base = ci2 + RADIUS * SW;
        #pragma unroll
        for (int dx = -RADIUS; dx <= RADIUS; dx++) {
            const int    j  = base + dx;
            const float  r  = s_img[j];
            const float4 q  = s_lab[j];
            const float  d2 = r - c2;
            const float  w2 = ex2(fmaf(d2 * d2, C_INT,
                                       C_DST * (float)(RADIUS * RADIUS + dx * dx)));
            S1b += w2;
            b0 = fmaf(w2, q.x, b0); b1 = fmaf(w2, q.y, b1);
            b2 = fmaf(w2, q.z, b2); b3 = fmaf(w2, q.w, b3);
        }
    }

    // Symmetric closure (w_ii = 1), both centers summed:
    //   A_k += p_k*(p_k + 2*S2_k);   B_k += p_k*(1+S1) + S2_k
    const float g1a = 1.f + S1a;
    const float g1b = 1.f + S1b;
    float v[8] = {
        p1.x * fmaf(2.f, a0, p1.x) + p2.x * fmaf(2.f, b0, p2.x),
        p1.y * fmaf(2.f, a1, p1.y) + p2.y * fmaf(2.f, b1, p2.y),
        p1.z * fmaf(2.f, a2, p1.z) + p2.z * fmaf(2.f, b2, p2.z),
        p1.w * fmaf(2.f, a3, p1.w) + p2.w * fmaf(2.f, b3, p2.w),
        fmaf(p1.x, g1a, a0) + fmaf(p2.x, g1b, b0),
        fmaf(p1.y, g1a, a1) + fmaf(p2.y, g1b, b1),
        fmaf(p1.z, g1a, a2) + fmaf(p2.z, g1b, b2),
        fmaf(p1.w, g1a, a3) + fmaf(p2.w, g1b, b3)
    };

    #pragma unroll
    for (int jj = 0; jj < 8; jj++) {
        float s = v[jj];
        #pragma unroll
        for (int o = 16; o > 0; o >>= 1)
            s += __shfl_xor_sync(0xffffffffu, s, o);
        if (tx == 0) s_red[ty][jj] = s;
    }
    __syncthreads();

    if (tid < 8) {
        float s = 0.f;
        #pragma unroll
        for (int w = 0; w < TY; w++) s += s_red[w][tid];
        const int k     = tid & 3;
        const int which = tid >> 2;   // 0 = A (num), 1 = B (den)
        atomicAdd(&g_acc[(b * NK + k) * 2 + which], (double)s);
    }

    // ---- last-block finalize ----
    __threadfence();
    if (tid == 0)
        s_last = (atomicAdd(&g_count, 1u) == NBLK - 1u);
    __syncthreads();

    if (s_last) {
        __threadfence();
        if (tid < NB * NK) {           // 32 parallel double divides
            double A  = g_acc[tid * 2 + 0];
            double Bv = g_acc[tid * 2 + 1];
            double r  = fabs(A / Bv);
            #pragma unroll
            for (int o = 16; o > 0; o >>= 1)
                r += __shfl_xor_sync(0xffffffffu, r, o);
            if (tid == 0)
                out[0] = (float)((double)NK - r / (double)NB);
        }
        __syncthreads();
        if (tid < NB * NK * 2) g_acc[tid] = 0.0;
        if (tid == 0) g_count = 0u;
    }
}

extern "C" void kernel_launch(void* const* d_in, const int* in_sizes, int n_in,
                              void* d_out, int out_size) {
    const float* images = (const float*)d_in[0];
    const float* labels = (const float*)d_in[1];
    if (n_in >= 2 && in_sizes[0] > in_sizes[1]) {   // robust to input ordering
        images = (const float*)d_in[1];
        labels = (const float*)d_in[0];
    }

    dim3 grid(IMW / TX, IMH / PY, NB);
    dim3 blk(TX, TY);
    k_main<<<grid, blk>>>(images, labels, (float*)d_out);
}

// round 7
// speedup vs baseline: 2.9066x; 1.0934x over previous
#include <cuda_runtime.h>

#define RADIUS 5
#define TX     32
#define TY     8                     /* threads in y; each owns 4 pixel rows */
#define NC     4                     /* centers per thread */
#define PY     (NC*TY)               /* 32 pixel rows per block */
#define SW     (TX + 2*RADIUS)       /* 42 */
#define SH     (PY + RADIUS)         /* 37: bottom halo only (symmetric pairs) */
#define NB     8
#define NK     4
#define IMH    224
#define IMW    224
#define NBLK   ((IMW/TX) * (IMH/PY) * NB)   /* 7*7*8 = 392 */

// Weight: exp2(-(s*(xr-xc))^2 + C_DST*(dy^2+dx^2)), s = 255*sqrt(log2e/100).
#define SCALE  (30.634556f)                  /* 255 * sqrt(log2(e)/100) */
#define C_DST  (-0.09016844005555897f)       /* -log2e / 16 */

__device__ __forceinline__ float ex2(float x) {
    float y;
    asm("ex2.approx.ftz.f32 %0, %1;" : "=f"(y) : "f"(x));
    return y;
}

// [b][k][{A,B}] accumulators (double) + completion counter. Zero at load;
// the last block resets them, so graph replays are deterministic.
__device__ double       g_acc[NB * NK * 2];
__device__ unsigned int g_count;

struct Ctr {
    float c;           // pre-scaled center intensity
    float4 p;          // center class probs
    float S1, s0, s1, s2, s3;
    __device__ __forceinline__ void init(float cc, float4 pp) {
        c = cc; p = pp; S1 = s0 = s1 = s2 = s3 = 0.f;
    }
    __device__ __forceinline__ void ev(float r, const float4& q, float dconst) {
        const float d = r - c;
        const float w = ex2(fmaf(-d, d, dconst));   // 1 FADD + 1 FFMA + 1 MUFU
        S1 += w;
        s0 = fmaf(w, q.x, s0); s1 = fmaf(w, q.y, s1);
        s2 = fmaf(w, q.z, s2); s3 = fmaf(w, q.w, s3);
    }
};

__global__ __launch_bounds__(TX * TY, 3) void k_main(const float* __restrict__ images,
                                                     const float* __restrict__ labels,
                                                     float* __restrict__ out) {
    __shared__ float  s_img[SH * SW];
    __shared__ float4 s_lab[SH * SW];
    __shared__ float  s_red[TY][8];
    __shared__ bool   s_last;

    const int tx  = threadIdx.x;
    const int ty  = threadIdx.y;
    const int tid = ty * TX + tx;
    const int b   = blockIdx.z;
    const int y0  = blockIdx.y * PY;
    const int x0  = blockIdx.x * TX;

    const float* imgb = images + (size_t)b * IMH * IMW;
    const float* labb = labels + (size_t)b * NK * IMH * IMW;

    // Halo: y in [y0, y0+PY+RADIUS), x in [x0-RADIUS, x0+TX+RADIUS).
    // Out-of-image: sentinel 1e10 -> weight underflows to exactly 0
    // (implements the boundary mask symmetrically); labels 0.
    for (int i = tid; i < SH * SW; i += TX * TY) {
        int sy = i / SW;
        int sx = i - sy * SW;
        int gy = y0 + sy;
        int gx = x0 + sx - RADIUS;
        bool in = ((unsigned)gy < IMH) && ((unsigned)gx < IMW);
        int g = gy * IMW + gx;
        s_img[i] = in ? imgb[g] * SCALE : 1e10f;
        float4 L = make_float4(0.f, 0.f, 0.f, 0.f);
        if (in) {
            L.x = labb[0 * IMH * IMW + g];
            L.y = labb[1 * IMH * IMW + g];
            L.z = labb[2 * IMH * IMW + g];
            L.w = labb[3 * IMH * IMW + g];
        }
        s_lab[i] = L;
    }
    __syncthreads();

    // 4 vertically adjacent centers per thread: rows NC*ty + 0..3.
    Ctr A[NC];
    const int ci0 = (NC * ty) * SW + tx + RADIUS;
    #pragma unroll
    for (int k = 0; k < NC; k++)
        A[k].init(s_img[ci0 + k * SW], s_lab[ci0 + k * SW]);

    // Positive half-stencil over rows o = 0..NC-1+RADIUS; each shared-memory
    // point (o, dx) feeds every center k with 0 <= dy = o-k <= RADIUS
    // (dy == 0 restricted to dx >= 1). All loop bounds compile-time.
    #pragma unroll
    for (int o = 0; o <= NC - 1 + RADIUS; o++) {
        const int base = ci0 + o * SW;
        #pragma unroll
        for (int dx = -RADIUS; dx <= RADIUS; dx++) {
            if (o == 0 && dx < 1) continue;      // no consumer for this point
            const int    j = base + dx;
            const float  r = s_img[j];
            const float4 q = s_lab[j];
            #pragma unroll
            for (int k = 0; k < NC; k++) {
                const int dy = o - k;
                if (dy < 0 || dy > RADIUS) continue;
                if (dy == 0 && dx < 1) continue;
                A[k].ev(r, q, C_DST * (float)(dy * dy + dx * dx));
            }
        }
    }

    // Symmetric closure (w_ii = 1), summed over the NC centers:
    //   A_k += p_k*(p_k + 2*S2_k);   B_k += p_k*(1+S1) + S2_k
    float v[8] = {0.f, 0.f, 0.f, 0.f, 0.f, 0.f, 0.f, 0.f};
    #pragma unroll
    for (int k = 0; k < NC; k++) {
        const float g1 = 1.f + A[k].S1;
        v[0] += A[k].p.x * fmaf(2.f, A[k].s0, A[k].p.x);
        v[1] += A[k].p.y * fmaf(2.f, A[k].s1, A[k].p.y);
        v[2] += A[k].p.z * fmaf(2.f, A[k].s2, A[k].p.z);
        v[3] += A[k].p.w * fmaf(2.f, A[k].s3, A[k].p.w);
        v[4] += fmaf(A[k].p.x, g1, A[k].s0);
        v[5] += fmaf(A[k].p.y, g1, A[k].s1);
        v[6] += fmaf(A[k].p.z, g1, A[k].s2);
        v[7] += fmaf(A[k].p.w, g1, A[k].s3);
    }

    #pragma unroll
    for (int jj = 0; jj < 8; jj++) {
        float s = v[jj];
        #pragma unroll
        for (int o = 16; o > 0; o >>= 1)
            s += __shfl_xor_sync(0xffffffffu, s, o);
        if (tx == 0) s_red[ty][jj] = s;
    }
    __syncthreads();

    if (tid < 8) {
        float s = 0.f;
        #pragma unroll
        for (int w = 0; w < TY; w++) s += s_red[w][tid];
        const int k     = tid & 3;
        const int which = tid >> 2;   // 0 = A (num), 1 = B (den)
        atomicAdd(&g_acc[(b * NK + k) * 2 + which], (double)s);
    }

    // ---- last-block finalize ----
    __threadfence();
    if (tid == 0)
        s_last = (atomicAdd(&g_count, 1u) == NBLK - 1u);
    __syncthreads();

    if (s_last) {
        __threadfence();
        if (tid < NB * NK) {           // 32 parallel double divides
            double Av = g_acc[tid * 2 + 0];
            double Bv = g_acc[tid * 2 + 1];
            double r  = fabs(Av / Bv);
            #pragma unroll
            for (int o = 16; o > 0; o >>= 1)
                r += __shfl_xor_sync(0xffffffffu, r, o);
            if (tid == 0)
                out[0] = (float)((double)NK - r / (double)NB);
        }
        __syncthreads();
        if (tid < NB * NK * 2) g_acc[tid] = 0.0;
        if (tid == 0) g_count = 0u;
    }
}

extern "C" void kernel_launch(void* const* d_in, const int* in_sizes, int n_in,
                              void* d_out, int out_size) {
    const float* images = (const float*)d_in[0];
    const float* labels = (const float*)d_in[1];
    if (n_in >= 2 && in_sizes[0] > in_sizes[1]) {   // robust to input ordering
        images = (const float*)d_in[1];
        labels = (const float*)d_in[0];
    }

    dim3 grid(IMW / TX, IMH / PY, NB);
    dim3 blk(TX, TY);
    k_main<<<grid, blk>>>(images, labels, (float*)d_out);
}

// round 8
// speedup vs baseline: 3.1879x; 1.0968x over previous
#include <cuda_runtime.h>

#define RADIUS 5
#define TX     32
#define TY     7                     /* threads in y; each owns 4 pixel rows */
#define NC     4                     /* centers per thread */
#define PY     (NC*TY)               /* 28 pixel rows per block */
#define SW     (TX + 2*RADIUS)       /* 42 */
#define SH     (PY + RADIUS)         /* 33: bottom halo only (symmetric pairs) */
#define NB     8
#define NK     4
#define IMH    224
#define IMW    224
#define NBLK   ((IMW/TX) * (IMH/PY) * NB)   /* 7*8*8 = 448 = 3.03 blocks/SM */

// Weight: exp2(-(s*(xr-xc))^2 + C_DST*(dy^2+dx^2)), s = 255*sqrt(log2e/100).
#define SCALE  (30.634556f)                  /* 255 * sqrt(log2(e)/100) */
#define C_DST  (-0.09016844005555897f)       /* -log2e / 16 */

__device__ __forceinline__ float ex2(float x) {
    float y;
    asm("ex2.approx.ftz.f32 %0, %1;" : "=f"(y) : "f"(x));
    return y;
}

// Packed fp32x2 helpers (FFMA2 is only reachable via explicit PTX).
__device__ __forceinline__ unsigned long long pack2(float lo, float hi) {
    unsigned long long v;
    asm("mov.b64 %0, {%1, %2};" : "=l"(v) : "f"(lo), "f"(hi));
    return v;
}
__device__ __forceinline__ void unpack2(unsigned long long v, float& lo, float& hi) {
    asm("mov.b64 {%0, %1}, %2;" : "=f"(lo), "=f"(hi) : "l"(v));
}
__device__ __forceinline__ void ffma2(unsigned long long& acc,
                                      unsigned long long a, unsigned long long b) {
    asm("fma.rn.f32x2 %0, %1, %2, %0;" : "+l"(acc) : "l"(a), "l"(b));
}

// [b][k][{A,B}] accumulators (double) + completion counter. Zero at load;
// the last block resets them, so graph replays are deterministic.
__device__ double       g_acc[NB * NK * 2];
__device__ unsigned int g_count;

struct Ctr {
    float c;                      // pre-scaled center intensity
    float4 p;                     // center class probs
    float S1;                     // sum of weights (positive offsets)
    unsigned long long s01, s23;  // packed (s0,s1), (s2,s3) accumulators
    __device__ __forceinline__ void init(float cc, float4 pp) {
        c = cc; p = pp; S1 = 0.f; s01 = 0ull; s23 = 0ull;
    }
    __device__ __forceinline__ void ev(float r, unsigned long long q01,
                                       unsigned long long q23, float dconst) {
        const float d = r - c;
        const float w = ex2(fmaf(-d, d, dconst));
        S1 += w;
        const unsigned long long w2 = pack2(w, w);
        ffma2(s01, w2, q01);
        ffma2(s23, w2, q23);
    }
};

__global__ __launch_bounds__(TX * TY, 3) void k_main(const float* __restrict__ images,
                                                     const float* __restrict__ labels,
                                                     float* __restrict__ out) {
    __shared__ float  s_img[SH * SW];
    __shared__ float4 s_lab[SH * SW];
    __shared__ float  s_red[TY][8];
    __shared__ bool   s_last;

    const int tx  = threadIdx.x;
    const int ty  = threadIdx.y;
    const int tid = ty * TX + tx;
    const int b   = blockIdx.z;
    const int y0  = blockIdx.y * PY;
    const int x0  = blockIdx.x * TX;

    const float* imgb = images + (size_t)b * IMH * IMW;
    const float* labb = labels + (size_t)b * NK * IMH * IMW;

    // Halo: y in [y0, y0+PY+RADIUS), x in [x0-RADIUS, x0+TX+RADIUS).
    // Out-of-image: sentinel 1e10 -> weight underflows to exactly 0
    // (implements the boundary mask symmetrically); labels 0.
    for (int i = tid; i < SH * SW; i += TX * TY) {
        int sy = i / SW;
        int sx = i - sy * SW;
        int gy = y0 + sy;
        int gx = x0 + sx - RADIUS;
        bool in = ((unsigned)gy < IMH) && ((unsigned)gx < IMW);
        int g = gy * IMW + gx;
        s_img[i] = in ? imgb[g] * SCALE : 1e10f;
        float4 L = make_float4(0.f, 0.f, 0.f, 0.f);
        if (in) {
            L.x = labb[0 * IMH * IMW + g];
            L.y = labb[1 * IMH * IMW + g];
            L.z = labb[2 * IMH * IMW + g];
            L.w = labb[3 * IMH * IMW + g];
        }
        s_lab[i] = L;
    }
    __syncthreads();

    // 4 vertically adjacent centers per thread: rows NC*ty + 0..3.
    Ctr A[NC];
    const int ci0 = (NC * ty) * SW + tx + RADIUS;
    #pragma unroll
    for (int k = 0; k < NC; k++)
        A[k].init(s_img[ci0 + k * SW], s_lab[ci0 + k * SW]);

    // Positive half-stencil over rows o = 0..NC-1+RADIUS; each shared-memory
    // point (o, dx) feeds every center k with 0 <= dy = o-k <= RADIUS
    // (dy == 0 restricted to dx >= 1). All loop bounds compile-time.
    #pragma unroll
    for (int o = 0; o <= NC - 1 + RADIUS; o++) {
        const int base = ci0 + o * SW;
        #pragma unroll
        for (int dx = -RADIUS; dx <= RADIUS; dx++) {
            if (o == 0 && dx < 1) continue;      // no consumer for this point
            const int    j = base + dx;
            const float  r = s_img[j];
            const float4 q = s_lab[j];
            const unsigned long long q01 = pack2(q.x, q.y);
            const unsigned long long q23 = pack2(q.z, q.w);
            #pragma unroll
            for (int k = 0; k < NC; k++) {
                const int dy = o - k;
                if (dy < 0 || dy > RADIUS) continue;
                if (dy == 0 && dx < 1) continue;
                A[k].ev(r, q01, q23, C_DST * (float)(dy * dy + dx * dx));
            }
        }
    }

    // Symmetric closure (w_ii = 1), summed over the NC centers:
    //   A_k += p_k*(p_k + 2*S2_k);   B_k += p_k*(1+S1) + S2_k
    float v[8] = {0.f, 0.f, 0.f, 0.f, 0.f, 0.f, 0.f, 0.f};
    #pragma unroll
    for (int k = 0; k < NC; k++) {
        float s0, s1, s2, s3;
        unpack2(A[k].s01, s0, s1);
        unpack2(A[k].s23, s2, s3);
        const float g1 = 1.f + A[k].S1;
        v[0] += A[k].p.x * fmaf(2.f, s0, A[k].p.x);
        v[1] += A[k].p.y * fmaf(2.f, s1, A[k].p.y);
        v[2] += A[k].p.z * fmaf(2.f, s2, A[k].p.z);
        v[3] += A[k].p.w * fmaf(2.f, s3, A[k].p.w);
        v[4] += fmaf(A[k].p.x, g1, s0);
        v[5] += fmaf(A[k].p.y, g1, s1);
        v[6] += fmaf(A[k].p.z, g1, s2);
        v[7] += fmaf(A[k].p.w, g1, s3);
    }

    #pragma unroll
    for (int jj = 0; jj < 8; jj++) {
        float s = v[jj];
        #pragma unroll
        for (int o = 16; o > 0; o >>= 1)
            s += __shfl_xor_sync(0xffffffffu, s, o);
        if (tx == 0) s_red[ty][jj] = s;
    }
    __syncthreads();

    if (tid < 8) {
        float s = 0.f;
        #pragma unroll
        for (int w = 0; w < TY; w++) s += s_red[w][tid];
        const int k     = tid & 3;
        const int which = tid >> 2;   // 0 = A (num), 1 = B (den)
        atomicAdd(&g_acc[(b * NK + k) * 2 + which], (double)s);
    }

    // ---- last-block finalize ----
    __threadfence();
    if (tid == 0)
        s_last = (atomicAdd(&g_count, 1u) == NBLK - 1u);
    __syncthreads();

    if (s_last) {
        __threadfence();
        if (tid < NB * NK) {           // 32 parallel double divides
            double Av = g_acc[tid * 2 + 0];
            double Bv = g_acc[tid * 2 + 1];
            double r  = fabs(Av / Bv);
            #pragma unroll
            for (int o = 16; o > 0; o >>= 1)
                r += __shfl_xor_sync(0xffffffffu, r, o);
            if (tid == 0)
                out[0] = (float)((double)NK - r / (double)NB);
        }
        __syncthreads();
        if (tid < NB * NK * 2) g_acc[tid] = 0.0;
        if (tid == 0) g_count = 0u;
    }
}

extern "C" void kernel_launch(void* const* d_in, const int* in_sizes, int n_in,
                              void* d_out, int out_size) {
    const float* images = (const float*)d_in[0];
    const float* labels = (const float*)d_in[1];
    if (n_in >= 2 && in_sizes[0] > in_sizes[1]) {   // robust to input ordering
        images = (const float*)d_in[1];
        labels = (const float*)d_in[0];
    }

    dim3 grid(IMW / TX, IMH / PY, NB);
    dim3 blk(TX, TY);
    k_main<<<grid, blk>>>(images, labels, (float*)d_out);
}